// round 1
// baseline (speedup 1.0000x reference)
#include <cuda_runtime.h>

#define DD 256
#define KK 32
#define NWARPS 8
#define ROWS_PER_WARP 8          // processed 2 at a time
#define ROWS_PER_BLOCK (NWARPS * ROWS_PER_WARP)   // 64

typedef unsigned long long u64;

__device__ __forceinline__ u64 pack2(float lo, float hi) {
    u64 r;
    asm("mov.b64 %0, {%1, %2};" : "=l"(r) : "f"(lo), "f"(hi));
    return r;
}
__device__ __forceinline__ float2 unpack2(u64 v) {
    float2 f;
    asm("mov.b64 {%0, %1}, %2;" : "=f"(f.x), "=f"(f.y) : "l"(v));
    return f;
}
__device__ __forceinline__ u64 fma2(u64 a, u64 b, u64 c) {
    u64 d;
    asm("fma.rn.f32x2 %0, %1, %2, %3;" : "=l"(d) : "l"(a), "l"(b), "l"(c));
    return d;
}
__device__ __forceinline__ u64 add2(u64 a, u64 b) {
    u64 d;
    asm("add.rn.f32x2 %0, %1, %2;" : "=l"(d) : "l"(a), "l"(b));
    return d;
}

__global__ void __launch_bounds__(256)
hh_kernel(const float* __restrict__ in,
          const float* __restrict__ qv,
          float* __restrict__ out,
          int n_rows) {
    __shared__ float qs[KK * DD];      // 32 KB
    __shared__ float scale[KK];

    const int tid = threadIdx.x;

    // Stage q vectors into SMEM (vectorized)
    {
        const float4* qg = (const float4*)qv;
        float4* qsh = (float4*)qs;
        #pragma unroll
        for (int i = tid; i < KK * DD / 4; i += 256) qsh[i] = qg[i];
    }
    __syncthreads();

    // Compute 2/||q_k||^2 (one thread per k; tiny one-time cost per block)
    if (tid < KK) {
        float s = 0.f;
        #pragma unroll 8
        for (int d = 0; d < DD; d++) { float v = qs[tid * DD + d]; s = fmaf(v, v, s); }
        scale[tid] = 2.0f / s;
    }
    __syncthreads();

    const int warp = tid >> 5;
    const int lane = tid & 31;
    const long long base_row = (long long)blockIdx.x * ROWS_PER_BLOCK
                             + (long long)warp * ROWS_PER_WARP;
    const float4* q4 = (const float4*)qs;

    for (int rp = 0; rp < ROWS_PER_WARP; rp += 2) {
        long long rowA = base_row + rp;
        if (rowA >= n_rows) break;
        long long rowB = rowA + 1;
        bool hasB = (rowB < n_rows);
        long long rB = hasB ? rowB : rowA;

        // Load rows: lane owns elements [4*lane,4*lane+4) and [128+4*lane, ...)
        const float4* xa = (const float4*)(in + rowA * DD);
        const float4* xb = (const float4*)(in + rB * DD);
        float4 a0 = xa[lane], a1 = xa[lane + 32];
        float4 b0 = xb[lane], b1 = xb[lane + 32];

        u64 A0 = pack2(a0.x, a0.y), A1 = pack2(a0.z, a0.w);
        u64 A2 = pack2(a1.x, a1.y), A3 = pack2(a1.z, a1.w);
        u64 B0 = pack2(b0.x, b0.y), B1 = pack2(b0.z, b0.w);
        u64 B2 = pack2(b1.x, b1.y), B3 = pack2(b1.z, b1.w);

        #pragma unroll 4
        for (int k = 0; k < KK; k++) {
            float4 qk0 = q4[k * 64 + lane];
            float4 qk1 = q4[k * 64 + lane + 32];
            u64 Q0 = pack2(qk0.x, qk0.y), Q1 = pack2(qk0.z, qk0.w);
            u64 Q2 = pack2(qk1.x, qk1.y), Q3 = pack2(qk1.z, qk1.w);

            // Packed partial dots (2 chains each for ILP)
            u64 da0 = fma2(A0, Q0, 0ull); da0 = fma2(A2, Q2, da0);
            u64 da1 = fma2(A1, Q1, 0ull); da1 = fma2(A3, Q3, da1);
            u64 db0 = fma2(B0, Q0, 0ull); db0 = fma2(B2, Q2, db0);
            u64 db1 = fma2(B1, Q1, 0ull); db1 = fma2(B3, Q3, db1);
            float2 fa = unpack2(add2(da0, da1));
            float2 fb = unpack2(add2(db0, db1));
            float sA = fa.x + fa.y;
            float sB = fb.x + fb.y;

            // Butterfly reduction across warp (both rows in flight)
            #pragma unroll
            for (int off = 16; off > 0; off >>= 1) {
                sA += __shfl_xor_sync(0xFFFFFFFFu, sA, off);
                sB += __shfl_xor_sync(0xFFFFFFFFu, sB, off);
            }

            float sc = scale[k];
            float cA = -sA * sc;
            float cB = -sB * sc;
            u64 CA = pack2(cA, cA);
            u64 CB = pack2(cB, cB);

            // Rank-1 update: x += c * q  (packed)
            A0 = fma2(CA, Q0, A0); A1 = fma2(CA, Q1, A1);
            A2 = fma2(CA, Q2, A2); A3 = fma2(CA, Q3, A3);
            B0 = fma2(CB, Q0, B0); B1 = fma2(CB, Q1, B1);
            B2 = fma2(CB, Q2, B2); B3 = fma2(CB, Q3, B3);
        }

        // Store
        float2 t;
        float4 o;
        t = unpack2(A0); o.x = t.x; o.y = t.y;
        t = unpack2(A1); o.z = t.x; o.w = t.y;
        ((float4*)(out + rowA * DD))[lane] = o;
        t = unpack2(A2); o.x = t.x; o.y = t.y;
        t = unpack2(A3); o.z = t.x; o.w = t.y;
        ((float4*)(out + rowA * DD))[lane + 32] = o;

        if (hasB) {
            t = unpack2(B0); o.x = t.x; o.y = t.y;
            t = unpack2(B1); o.z = t.x; o.w = t.y;
            ((float4*)(out + rowB * DD))[lane] = o;
            t = unpack2(B2); o.x = t.x; o.y = t.y;
            t = unpack2(B3); o.z = t.x; o.w = t.y;
            ((float4*)(out + rowB * DD))[lane + 32] = o;
        }
    }
}

__global__ void zero_tail_kernel(float* __restrict__ out, long long start, long long end) {
    long long i = start + (long long)blockIdx.x * blockDim.x + threadIdx.x;
    if (i < end) out[i] = 0.0f;
}

extern "C" void kernel_launch(void* const* d_in, const int* in_sizes, int n_in,
                              void* d_out, int out_size) {
    const float* inp = (const float*)d_in[0];   // inputs  [N, 256]
    const float* qv  = (const float*)d_in[1];   // q_vectors [32, 256]
    float* out = (float*)d_out;

    int n_rows = in_sizes[0] / DD;

    int grid = (n_rows + ROWS_PER_BLOCK - 1) / ROWS_PER_BLOCK;
    hh_kernel<<<grid, 256>>>(inp, qv, out, n_rows);

    long long nd = (long long)n_rows * DD;
    long long total = (long long)out_size;
    if (total > nd) {
        long long tail = total - nd;
        int zgrid = (int)((tail + 255) / 256);
        zero_tail_kernel<<<zgrid, 256>>>(out, nd, total);
    }
}